// round 1
// baseline (speedup 1.0000x reference)
#include <cuda_runtime.h>
#include <math.h>

// ---------------------------------------------------------------------------
// SimpleTransformerBlock: B=4, L=4096, D=1024, H=16, Dh=64
// attention is PER-POSITION head mixing (einsum over d at same l).
// Heavy work = 4 GEMMs (412 GFLOP fp32). Round 1: fp32 tiled SGEMM baseline.
// ---------------------------------------------------------------------------

#define D_MODEL 1024
#define M_ROWS  16384           // 4 * 4096

// Scratch (device globals; no runtime allocation allowed)
__device__ float g_h   [(size_t)M_ROWS * 1024];   // ln1 out / ln2 out
__device__ float g_qkv [(size_t)M_ROWS * 3072];
__device__ float g_attn[(size_t)M_ROWS * 1024];
__device__ float g_x1  [(size_t)M_ROWS * 1024];   // x + attn proj
__device__ float g_mlp [(size_t)M_ROWS * 4096];

// ---------------------------------------------------------------------------
// LayerNorm over rows of 1024. One block (256 thr) per row, float4 per thread.
// ---------------------------------------------------------------------------
__global__ __launch_bounds__(256) void ln_kernel(
    const float* __restrict__ x, const float* __restrict__ w,
    const float* __restrict__ b, float* __restrict__ out)
{
    const int row = blockIdx.x;
    const int t   = threadIdx.x;
    const float4 v = ((const float4*)(x + (size_t)row * 1024))[t];

    float s  = v.x + v.y + v.z + v.w;
    float sq = v.x*v.x + v.y*v.y + v.z*v.z + v.w*v.w;
    #pragma unroll
    for (int o = 16; o > 0; o >>= 1) {
        s  += __shfl_xor_sync(0xffffffffu, s,  o);
        sq += __shfl_xor_sync(0xffffffffu, sq, o);
    }
    __shared__ float sm[8], sm2[8];
    const int warp = t >> 5, lane = t & 31;
    if (lane == 0) { sm[warp] = s; sm2[warp] = sq; }
    __syncthreads();
    if (t == 0) {
        float a = 0.f, c = 0.f;
        #pragma unroll
        for (int i = 0; i < 8; i++) { a += sm[i]; c += sm2[i]; }
        sm[0] = a; sm2[0] = c;
    }
    __syncthreads();
    const float mean = sm[0]  * (1.f / 1024.f);
    const float var  = sm2[0] * (1.f / 1024.f) - mean * mean;
    const float inv  = rsqrtf(var + 1e-5f);

    const float4 wv = ((const float4*)w)[t];
    const float4 bv = ((const float4*)b)[t];
    float4 o;
    o.x = (v.x - mean) * inv * wv.x + bv.x;
    o.y = (v.y - mean) * inv * wv.y + bv.y;
    o.z = (v.z - mean) * inv * wv.z + bv.z;
    o.w = (v.w - mean) * inv * wv.w + bv.w;
    ((float4*)(out + (size_t)row * 1024))[t] = o;
}

// ---------------------------------------------------------------------------
// Per-position head-mix attention. One block (128 thr) per token position.
// q,k,v each [16 heads][64] taken from the 3072-wide qkv row.
// ---------------------------------------------------------------------------
__global__ __launch_bounds__(128) void attn_kernel(
    const float* __restrict__ qkv, float* __restrict__ out)
{
    const int pos = blockIdx.x;
    const int t   = threadIdx.x;
    const float* base = qkv + (size_t)pos * 3072;

    __shared__ float sq[1024], sk[1024], sv[1024];
    __shared__ float S[16][17];

    #pragma unroll
    for (int i = t; i < 1024; i += 128) {
        sq[i] = base[i];
        sk[i] = base[1024 + i];
        sv[i] = base[2048 + i];
    }
    __syncthreads();

    // scores S[h][g] = q[h].k[g] / 8
    for (int e = t; e < 256; e += 128) {
        const int h = e >> 4, g = e & 15;
        float acc = 0.f;
        #pragma unroll
        for (int d = 0; d < 64; d++) acc += sq[h * 64 + d] * sk[g * 64 + d];
        S[h][g] = acc * 0.125f;
    }
    __syncthreads();

    // softmax over g, one thread per row h
    if (t < 16) {
        float m = -1e30f;
        #pragma unroll
        for (int g = 0; g < 16; g++) m = fmaxf(m, S[t][g]);
        float sum = 0.f;
        #pragma unroll
        for (int g = 0; g < 16; g++) { float e = expf(S[t][g] - m); S[t][g] = e; sum += e; }
        const float inv = 1.f / sum;
        #pragma unroll
        for (int g = 0; g < 16; g++) S[t][g] *= inv;
    }
    __syncthreads();

    // out[h][d] = sum_g P[h][g] * v[g][d]
    for (int o = t; o < 1024; o += 128) {
        const int h = o >> 6, d = o & 63;
        float acc = 0.f;
        #pragma unroll
        for (int g = 0; g < 16; g++) acc += S[h][g] * sv[g * 64 + d];
        out[(size_t)pos * 1024 + o] = acc;
    }
}

// ---------------------------------------------------------------------------
// SGEMM: C[M,N] = A[M,K] @ W[N,K]^T + bias (+ residual / gelu)
// BM=BN=128, BK=8, 256 threads, 8x8 microtile, double-buffered smem.
// All problem dims are multiples of the tiles -> no bounds checks.
// ---------------------------------------------------------------------------
#define BM 128
#define BN 128
#define BK 8

#define EPI_BIAS 0
#define EPI_RES  1
#define EPI_GELU 2

__device__ __forceinline__ float gelu_exact(float v) {
    return 0.5f * v * (1.0f + erff(v * 0.70710678118654752f));
}

template<int EPI>
__global__ __launch_bounds__(256, 2) void sgemm_kernel(
    int M, int N, int K,
    const float* __restrict__ A,     // [M,K]
    const float* __restrict__ W,     // [N,K]
    const float* __restrict__ bias,  // [N]
    const float* __restrict__ res,   // [M,N] or null
    float* __restrict__ C)           // [M,N]
{
    __shared__ float As[2][BK][BM];
    __shared__ float Bs[2][BK][BN];

    const int bm  = blockIdx.y * BM;
    const int bn  = blockIdx.x * BN;
    const int tid = threadIdx.x;

    const int lr = tid >> 1;           // 0..127  (tile row for loads)
    const int lc = (tid & 1) << 2;     // 0 or 4  (k offset for loads)

    const float* Ag = A + (size_t)(bm + lr) * K + lc;
    const float* Wg = W + (size_t)(bn + lr) * K + lc;

    const int tx = tid & 15;
    const int ty = tid >> 4;

    float acc[8][8];
    #pragma unroll
    for (int i = 0; i < 8; i++)
        #pragma unroll
        for (int j = 0; j < 8; j++) acc[i][j] = 0.f;

    // prologue: tile 0
    {
        const float4 a = *(const float4*)Ag;
        const float4 b = *(const float4*)Wg;
        As[0][lc+0][lr] = a.x; As[0][lc+1][lr] = a.y;
        As[0][lc+2][lr] = a.z; As[0][lc+3][lr] = a.w;
        Bs[0][lc+0][lr] = b.x; Bs[0][lc+1][lr] = b.y;
        Bs[0][lc+2][lr] = b.z; Bs[0][lc+3][lr] = b.w;
    }
    __syncthreads();

    int buf = 0;
    for (int k0 = BK; k0 < K + BK; k0 += BK) {
        if (k0 < K) {
            const float4 a = *(const float4*)(Ag + k0);
            const float4 b = *(const float4*)(Wg + k0);
            const int nb = buf ^ 1;
            As[nb][lc+0][lr] = a.x; As[nb][lc+1][lr] = a.y;
            As[nb][lc+2][lr] = a.z; As[nb][lc+3][lr] = a.w;
            Bs[nb][lc+0][lr] = b.x; Bs[nb][lc+1][lr] = b.y;
            Bs[nb][lc+2][lr] = b.z; Bs[nb][lc+3][lr] = b.w;
        }
        #pragma unroll
        for (int kk = 0; kk < BK; kk++) {
            float af[8], bf[8];
            *(float4*)&af[0] = *(const float4*)&As[buf][kk][ty * 8];
            *(float4*)&af[4] = *(const float4*)&As[buf][kk][ty * 8 + 4];
            *(float4*)&bf[0] = *(const float4*)&Bs[buf][kk][tx * 8];
            *(float4*)&bf[4] = *(const float4*)&Bs[buf][kk][tx * 8 + 4];
            #pragma unroll
            for (int i = 0; i < 8; i++)
                #pragma unroll
                for (int j = 0; j < 8; j++)
                    acc[i][j] = fmaf(af[i], bf[j], acc[i][j]);
        }
        buf ^= 1;
        __syncthreads();
    }

    // epilogue
    const int row0 = bm + ty * 8;
    const int col0 = bn + tx * 8;
    float bias8[8];
    *(float4*)&bias8[0] = *(const float4*)(bias + col0);
    *(float4*)&bias8[4] = *(const float4*)(bias + col0 + 4);

    #pragma unroll
    for (int i = 0; i < 8; i++) {
        const size_t off = (size_t)(row0 + i) * N + col0;
        float v[8];
        #pragma unroll
        for (int j = 0; j < 8; j++) v[j] = acc[i][j] + bias8[j];
        if (EPI == EPI_RES) {
            float r[8];
            *(float4*)&r[0] = *(const float4*)(res + off);
            *(float4*)&r[4] = *(const float4*)(res + off + 4);
            #pragma unroll
            for (int j = 0; j < 8; j++) v[j] += r[j];
        }
        if (EPI == EPI_GELU) {
            #pragma unroll
            for (int j = 0; j < 8; j++) v[j] = gelu_exact(v[j]);
        }
        *(float4*)(C + off)     = *(float4*)&v[0];
        *(float4*)(C + off + 4) = *(float4*)&v[4];
    }
}

// ---------------------------------------------------------------------------
// Launch
// ---------------------------------------------------------------------------
extern "C" void kernel_launch(void* const* d_in, const int* in_sizes, int n_in,
                              void* d_out, int out_size)
{
    const float* x      = (const float*)d_in[0];
    const float* qkv_w  = (const float*)d_in[1];
    const float* qkv_b  = (const float*)d_in[2];
    const float* proj_w = (const float*)d_in[3];
    const float* proj_b = (const float*)d_in[4];
    const float* ln1_w  = (const float*)d_in[5];
    const float* ln1_b  = (const float*)d_in[6];
    const float* ln2_w  = (const float*)d_in[7];
    const float* ln2_b  = (const float*)d_in[8];
    const float* mlp_w1 = (const float*)d_in[9];
    const float* mlp_b1 = (const float*)d_in[10];
    const float* mlp_w2 = (const float*)d_in[11];
    const float* mlp_b2 = (const float*)d_in[12];
    float* out = (float*)d_out;

    float *h, *qkv, *attn, *x1, *mlp;
    cudaGetSymbolAddress((void**)&h,    g_h);
    cudaGetSymbolAddress((void**)&qkv,  g_qkv);
    cudaGetSymbolAddress((void**)&attn, g_attn);
    cudaGetSymbolAddress((void**)&x1,   g_x1);
    cudaGetSymbolAddress((void**)&mlp,  g_mlp);

    const int M = M_ROWS;

    // 1) h = LN1(x)
    ln_kernel<<<M, 256>>>(x, ln1_w, ln1_b, h);

    // 2) qkv = h @ qkv_w^T + qkv_b        [16384, 3072]
    sgemm_kernel<EPI_BIAS><<<dim3(3072 / BN, M / BM), 256>>>(
        M, 3072, 1024, h, qkv_w, qkv_b, nullptr, qkv);

    // 3) per-position head-mix attention  -> attn [16384, 1024]
    attn_kernel<<<M, 128>>>(qkv, attn);

    // 4) x1 = x + attn @ proj_w^T + proj_b
    sgemm_kernel<EPI_RES><<<dim3(1024 / BN, M / BM), 256>>>(
        M, 1024, 1024, attn, proj_w, proj_b, x, x1);

    // 5) h = LN2(x1)
    ln_kernel<<<M, 256>>>(x1, ln2_w, ln2_b, h);

    // 6) mlp = gelu(h @ mlp_w1^T + mlp_b1)   [16384, 4096]
    sgemm_kernel<EPI_GELU><<<dim3(4096 / BN, M / BM), 256>>>(
        M, 4096, 1024, h, mlp_w1, mlp_b1, nullptr, mlp);

    // 7) out = x1 + mlp @ mlp_w2^T + mlp_b2
    sgemm_kernel<EPI_RES><<<dim3(1024 / BN, M / BM), 256>>>(
        M, 1024, 4096, mlp, mlp_w2, mlp_b2, x1, out);
}

// round 3
// speedup vs baseline: 2.7440x; 2.7440x over previous
#include <cuda_runtime.h>
#include <cuda_bf16.h>
#include <cstdint>
#include <math.h>

// ---------------------------------------------------------------------------
// SimpleTransformerBlock via warp-level bf16 mma.sync (sm_80 ISA; the harness
// PTX target is sm_103 non-'a', so tcgen05 is unavailable).
// fp32 accuracy via bf16 hi/lo split: A=[hi|hi|lo], B=[hi|lo|hi], K'=3K.
// ---------------------------------------------------------------------------

#define M_ROWS 16384

// fp32 scratch
__device__ float g_h   [(size_t)M_ROWS * 1024];   // attn out
__device__ float g_qkv [(size_t)M_ROWS * 3072];
__device__ float g_x1  [(size_t)M_ROWS * 1024];
__device__ float g_mlp [(size_t)M_ROWS * 4096];
// bf16 split scratch
__device__ __nv_bfloat16 g_act  [(size_t)M_ROWS * 3072];    // A split, K=1024
__device__ __nv_bfloat16 g_amlp [(size_t)M_ROWS * 12288];   // A split, K=4096
__device__ __nv_bfloat16 g_ws   [(size_t)4096 * 3072];      // B split (per GEMM)

// ---------------------------------------------------------------------------
// small PTX wrappers
// ---------------------------------------------------------------------------
__device__ __forceinline__ uint32_t smem_u32(const void* p) {
    uint32_t a;
    asm("{ .reg .u64 t; cvta.to.shared.u64 t, %1; cvt.u32.u64 %0, t; }" : "=r"(a) : "l"(p));
    return a;
}
__device__ __forceinline__ void cp_async16(uint32_t dst, const void* src) {
    asm volatile("cp.async.cg.shared.global [%0], [%1], 16;" :: "r"(dst), "l"(src));
}
__device__ __forceinline__ void cp_commit() {
    asm volatile("cp.async.commit_group;" ::: "memory");
}
__device__ __forceinline__ void cp_wait1() {
    asm volatile("cp.async.wait_group 1;" ::: "memory");
}
__device__ __forceinline__ void ldsm_x4(uint32_t* r, uint32_t addr) {
    asm volatile("ldmatrix.sync.aligned.m8n8.x4.shared.b16 {%0,%1,%2,%3}, [%4];"
                 : "=r"(r[0]), "=r"(r[1]), "=r"(r[2]), "=r"(r[3]) : "r"(addr));
}
__device__ __forceinline__ void mma16816(float* c, const uint32_t* a, uint32_t b0, uint32_t b1) {
    asm volatile(
        "mma.sync.aligned.m16n8k16.row.col.f32.bf16.bf16.f32 "
        "{%0,%1,%2,%3}, {%4,%5,%6,%7}, {%8,%9}, {%0,%1,%2,%3};"
        : "+f"(c[0]), "+f"(c[1]), "+f"(c[2]), "+f"(c[3])
        : "r"(a[0]), "r"(a[1]), "r"(a[2]), "r"(a[3]), "r"(b0), "r"(b1));
}
__device__ __forceinline__ uint32_t swz(uint32_t off) {   // SW128 (128B rows)
    return off ^ ((off >> 3) & 0x70);
}

// ---------------------------------------------------------------------------
// LayerNorm fused with hi/lo split: out row = [hi(1024) | hi(1024) | lo(1024)]
// ---------------------------------------------------------------------------
__global__ __launch_bounds__(256) void ln_split_kernel(
    const float* __restrict__ x, const float* __restrict__ w,
    const float* __restrict__ b, __nv_bfloat16* __restrict__ out)
{
    const int row = blockIdx.x;
    const int t   = threadIdx.x;
    const float4 v = ((const float4*)(x + (size_t)row * 1024))[t];
    float s  = v.x + v.y + v.z + v.w;
    float sq = v.x*v.x + v.y*v.y + v.z*v.z + v.w*v.w;
    #pragma unroll
    for (int o = 16; o > 0; o >>= 1) {
        s  += __shfl_xor_sync(0xffffffffu, s,  o);
        sq += __shfl_xor_sync(0xffffffffu, sq, o);
    }
    __shared__ float sm[8], sm2[8];
    const int warp = t >> 5, lane = t & 31;
    if (lane == 0) { sm[warp] = s; sm2[warp] = sq; }
    __syncthreads();
    if (t == 0) {
        float a = 0.f, c = 0.f;
        #pragma unroll
        for (int i = 0; i < 8; i++) { a += sm[i]; c += sm2[i]; }
        sm[0] = a; sm2[0] = c;
    }
    __syncthreads();
    const float mean = sm[0]  * (1.f / 1024.f);
    const float var  = sm2[0] * (1.f / 1024.f) - mean * mean;
    const float inv  = rsqrtf(var + 1e-5f);
    const float4 wv = ((const float4*)w)[t];
    const float4 bv = ((const float4*)b)[t];
    float o0 = (v.x - mean) * inv * wv.x + bv.x;
    float o1 = (v.y - mean) * inv * wv.y + bv.y;
    float o2 = (v.z - mean) * inv * wv.z + bv.z;
    float o3 = (v.w - mean) * inv * wv.w + bv.w;

    union { __nv_bfloat16 h[4]; uint2 u; } H, L;
    H.h[0] = __float2bfloat16(o0); H.h[1] = __float2bfloat16(o1);
    H.h[2] = __float2bfloat16(o2); H.h[3] = __float2bfloat16(o3);
    L.h[0] = __float2bfloat16(o0 - __bfloat162float(H.h[0]));
    L.h[1] = __float2bfloat16(o1 - __bfloat162float(H.h[1]));
    L.h[2] = __float2bfloat16(o2 - __bfloat162float(H.h[2]));
    L.h[3] = __float2bfloat16(o3 - __bfloat162float(H.h[3]));

    __nv_bfloat16* base = out + (size_t)row * 3072 + t * 4;
    *(uint2*)(base)        = H.u;
    *(uint2*)(base + 1024) = H.u;
    *(uint2*)(base + 2048) = L.u;
}

// ---------------------------------------------------------------------------
// fp32 -> bf16 hi/lo split. LO_BLK=2: [hi|hi|lo] (A); LO_BLK=1: [hi|lo|hi] (B)
// ---------------------------------------------------------------------------
template<int LO_BLK>
__global__ __launch_bounds__(256) void split_kernel(
    const float* __restrict__ in, __nv_bfloat16* __restrict__ out, int K)
{
    const size_t e = ((size_t)blockIdx.x * 256 + threadIdx.x) * 4;
    const size_t r = e / (size_t)K;
    const int    c = (int)(e - r * (size_t)K);
    const float4 v = *(const float4*)(in + e);

    union { __nv_bfloat16 b[4]; uint2 u; } H, L;
    H.b[0] = __float2bfloat16(v.x); H.b[1] = __float2bfloat16(v.y);
    H.b[2] = __float2bfloat16(v.z); H.b[3] = __float2bfloat16(v.w);
    L.b[0] = __float2bfloat16(v.x - __bfloat162float(H.b[0]));
    L.b[1] = __float2bfloat16(v.y - __bfloat162float(H.b[1]));
    L.b[2] = __float2bfloat16(v.z - __bfloat162float(H.b[2]));
    L.b[3] = __float2bfloat16(v.w - __bfloat162float(H.b[3]));

    __nv_bfloat16* base = out + r * (size_t)(3 * K) + c;
    *(uint2*)(base)         = H.u;
    *(uint2*)(base + K)     = (LO_BLK == 1) ? L.u : H.u;
    *(uint2*)(base + 2 * K) = (LO_BLK == 2) ? L.u : H.u;
}

// ---------------------------------------------------------------------------
// Per-position head-mix attention
// ---------------------------------------------------------------------------
__global__ __launch_bounds__(128) void attn_kernel(
    const float* __restrict__ qkv, float* __restrict__ out)
{
    const int pos = blockIdx.x;
    const int t   = threadIdx.x;
    const float* base = qkv + (size_t)pos * 3072;
    __shared__ float sq[1024], sk[1024], sv[1024];
    __shared__ float S[16][17];
    #pragma unroll
    for (int i = t; i < 1024; i += 128) {
        sq[i] = base[i]; sk[i] = base[1024 + i]; sv[i] = base[2048 + i];
    }
    __syncthreads();
    for (int e = t; e < 256; e += 128) {
        const int h = e >> 4, g = e & 15;
        float acc = 0.f;
        #pragma unroll
        for (int d = 0; d < 64; d++) acc += sq[h * 64 + d] * sk[g * 64 + d];
        S[h][g] = acc * 0.125f;
    }
    __syncthreads();
    if (t < 16) {
        float m = -1e30f;
        #pragma unroll
        for (int g = 0; g < 16; g++) m = fmaxf(m, S[t][g]);
        float sum = 0.f;
        #pragma unroll
        for (int g = 0; g < 16; g++) { float e = expf(S[t][g] - m); S[t][g] = e; sum += e; }
        const float inv = 1.f / sum;
        #pragma unroll
        for (int g = 0; g < 16; g++) S[t][g] *= inv;
    }
    __syncthreads();
    for (int o = t; o < 1024; o += 128) {
        const int h = o >> 6, d = o & 63;
        float acc = 0.f;
        #pragma unroll
        for (int g = 0; g < 16; g++) acc += S[h][g] * sv[g * 64 + d];
        out[(size_t)pos * 1024 + o] = acc;
    }
}

// ---------------------------------------------------------------------------
// bf16 mma.sync GEMM: C[M,N] = A[M,K3] @ B[N,K3]^T (+bias/res/gelu), fp32 acc
// BM=BN=128, BK=64, 256 thr (8 warps 4x2, warp tile 32x64), 3-stage cp.async.
// SMEM: per stage A(16KB)+B(16KB), SW128 swizzle (128B rows of 64 bf16).
// ---------------------------------------------------------------------------
#define STAGES 3
#define STAGE_BYTES 32768

#define EPI_BIAS 0
#define EPI_RES  1
#define EPI_GELU 2

__device__ __forceinline__ float gelu_exact(float v) {
    return 0.5f * v * (1.0f + erff(v * 0.70710678118654752f));
}

template<int EPI>
__global__ __launch_bounds__(256, 2) void gemm_mma(
    int M, int N, int K3,
    const __nv_bfloat16* __restrict__ A,   // [M, K3]
    const __nv_bfloat16* __restrict__ B,   // [N, K3]
    const float* __restrict__ bias,
    const float* __restrict__ res,
    float* __restrict__ C)
{
    extern __shared__ char smem[];
    const uint32_t sbase = smem_u32(smem);

    const int tid  = threadIdx.x;
    const int wid  = tid >> 5;
    const int lane = tid & 31;
    const int wm   = wid & 3;          // 0..3  -> m offset 32*wm
    const int wn   = wid >> 2;         // 0..1  -> n offset 64*wn

    const int bm = blockIdx.y * 128;
    const int bn = blockIdx.x * 128;
    const __nv_bfloat16* Ab = A + (size_t)bm * K3;
    const __nv_bfloat16* Bb = B + (size_t)bn * K3;

    float acc[2][8][4];
    #pragma unroll
    for (int i = 0; i < 2; i++)
        #pragma unroll
        for (int j = 0; j < 8; j++)
            #pragma unroll
            for (int k = 0; k < 4; k++) acc[i][j][k] = 0.f;

    // per-thread load coords: 4 chunks of 16B per operand per stage
    // chunk idx -> row = idx>>3, col16 = idx&7
    auto load_stage = [&](int k0, int buf) {
        const uint32_t sA = sbase + buf * STAGE_BYTES;
        const uint32_t sB = sA + 16384;
        #pragma unroll
        for (int i = 0; i < 4; i++) {
            const int idx = tid + (i << 8);
            const int row = idx >> 3;
            const int c8  = (idx & 7) << 3;      // bf16 col
            const uint32_t so = swz((uint32_t)(row * 128 + c8 * 2));
            cp_async16(sA + so, Ab + (size_t)row * K3 + k0 + c8);
            cp_async16(sB + so, Bb + (size_t)row * K3 + k0 + c8);
        }
    };

    const int S = K3 >> 6;
    load_stage(0, 0); cp_commit();
    load_stage(64, 1); cp_commit();

    for (int s = 0; s < S; s++) {
        cp_wait1();
        __syncthreads();

        if (s + STAGES - 1 < S) load_stage((s + STAGES - 1) << 6, (s + STAGES - 1) % STAGES);
        cp_commit();

        const uint32_t sA = sbase + (s % STAGES) * STAGE_BYTES;
        const uint32_t sB = sA + 16384;

        #pragma unroll
        for (int ks = 0; ks < 4; ks++) {
            const int chunk = ks * 2 + (lane >> 4);          // 16B col index
            uint32_t a[2][4];
            #pragma unroll
            for (int mt = 0; mt < 2; mt++) {
                const int row = wm * 32 + mt * 16 + (lane & 15);
                ldsm_x4(a[mt], sA + swz((uint32_t)(row * 128 + chunk * 16)));
            }
            uint32_t bfr[4][4];
            #pragma unroll
            for (int bt = 0; bt < 4; bt++) {
                const int row = wn * 64 + bt * 16 + (lane & 15);
                ldsm_x4(bfr[bt], sB + swz((uint32_t)(row * 128 + chunk * 16)));
            }
            #pragma unroll
            for (int mt = 0; mt < 2; mt++)
                #pragma unroll
                for (int nt = 0; nt < 8; nt++) {
                    const int bt = nt >> 1, wh = nt & 1;
                    mma16816(acc[mt][nt], a[mt], bfr[bt][wh], bfr[bt][wh + 2]);
                }
        }
        __syncthreads();
    }

    // epilogue: direct stores, 8B (float2) granularity
    const int colq = (lane & 3) * 2;
    const int rowq = lane >> 2;
    #pragma unroll
    for (int mt = 0; mt < 2; mt++) {
        #pragma unroll
        for (int nt = 0; nt < 8; nt++) {
            const int col = bn + wn * 64 + nt * 8 + colq;
            const float2 bz = *(const float2*)(bias + col);
            #pragma unroll
            for (int hh = 0; hh < 2; hh++) {
                const int grow = bm + wm * 32 + mt * 16 + rowq + hh * 8;
                float2 v;
                v.x = acc[mt][nt][hh * 2 + 0] + bz.x;
                v.y = acc[mt][nt][hh * 2 + 1] + bz.y;
                const size_t off = (size_t)grow * N + col;
                if (EPI == EPI_RES) {
                    const float2 r = *(const float2*)(res + off);
                    v.x += r.x; v.y += r.y;
                }
                if (EPI == EPI_GELU) {
                    v.x = gelu_exact(v.x); v.y = gelu_exact(v.y);
                }
                *(float2*)(C + off) = v;
            }
        }
    }
}

// ---------------------------------------------------------------------------
// Launch
// ---------------------------------------------------------------------------
extern "C" void kernel_launch(void* const* d_in, const int* in_sizes, int n_in,
                              void* d_out, int out_size)
{
    const float* x      = (const float*)d_in[0];
    const float* qkv_w  = (const float*)d_in[1];
    const float* qkv_b  = (const float*)d_in[2];
    const float* proj_w = (const float*)d_in[3];
    const float* proj_b = (const float*)d_in[4];
    const float* ln1_w  = (const float*)d_in[5];
    const float* ln1_b  = (const float*)d_in[6];
    const float* ln2_w  = (const float*)d_in[7];
    const float* ln2_b  = (const float*)d_in[8];
    const float* mlp_w1 = (const float*)d_in[9];
    const float* mlp_b1 = (const float*)d_in[10];
    const float* mlp_w2 = (const float*)d_in[11];
    const float* mlp_b2 = (const float*)d_in[12];
    float* out = (float*)d_out;

    float *h, *qkv, *x1, *mlp;
    __nv_bfloat16 *act, *amlp, *ws;
    cudaGetSymbolAddress((void**)&h,    g_h);
    cudaGetSymbolAddress((void**)&qkv,  g_qkv);
    cudaGetSymbolAddress((void**)&x1,   g_x1);
    cudaGetSymbolAddress((void**)&mlp,  g_mlp);
    cudaGetSymbolAddress((void**)&act,  g_act);
    cudaGetSymbolAddress((void**)&amlp, g_amlp);
    cudaGetSymbolAddress((void**)&ws,   g_ws);

    const int SMEM = STAGES * STAGE_BYTES;   // 96KB
    cudaFuncSetAttribute(gemm_mma<EPI_BIAS>, cudaFuncAttributeMaxDynamicSharedMemorySize, SMEM);
    cudaFuncSetAttribute(gemm_mma<EPI_RES>,  cudaFuncAttributeMaxDynamicSharedMemorySize, SMEM);
    cudaFuncSetAttribute(gemm_mma<EPI_GELU>, cudaFuncAttributeMaxDynamicSharedMemorySize, SMEM);

    const int M = M_ROWS;

    // 1) act = split(LN1(x))
    ln_split_kernel<<<M, 256>>>(x, ln1_w, ln1_b, act);

    // 2) qkv = act @ ws^T + qkv_b
    split_kernel<1><<<3072 * 1024 / 1024, 256>>>(qkv_w, ws, 1024);
    gemm_mma<EPI_BIAS><<<dim3(3072 / 128, M / 128), 256, SMEM>>>(
        M, 3072, 3072, act, ws, qkv_b, nullptr, qkv);

    // 3) attention -> h
    attn_kernel<<<M, 128>>>(qkv, h);

    // 4) x1 = x + h @ proj_w^T + proj_b
    split_kernel<2><<<(int)((size_t)M * 1024 / 1024), 256>>>(h, act, 1024);
    split_kernel<1><<<1024 * 1024 / 1024, 256>>>(proj_w, ws, 1024);
    gemm_mma<EPI_RES><<<dim3(1024 / 128, M / 128), 256, SMEM>>>(
        M, 1024, 3072, act, ws, proj_b, x, x1);

    // 5) act = split(LN2(x1))
    ln_split_kernel<<<M, 256>>>(x1, ln2_w, ln2_b, act);

    // 6) mlp = gelu(act @ mlp_w1^T + mlp_b1)
    split_kernel<1><<<4096 * 1024 / 1024, 256>>>(mlp_w1, ws, 1024);
    gemm_mma<EPI_GELU><<<dim3(4096 / 128, M / 128), 256, SMEM>>>(
        M, 4096, 3072, act, ws, mlp_b1, nullptr, mlp);

    // 7) out = x1 + amlp @ mlp_w2^T + mlp_b2
    split_kernel<2><<<(int)((size_t)M * 4096 / 1024), 256>>>(mlp, amlp, 4096);
    split_kernel<1><<<1024 * 4096 / 1024, 256>>>(mlp_w2, ws, 4096);
    gemm_mma<EPI_RES><<<dim3(1024 / 128, M / 128), 256, SMEM>>>(
        M, 1024, 12288, amlp, ws, mlp_b2, x1, out);
}

// round 4
// speedup vs baseline: 2.7823x; 1.0140x over previous
#include <cuda_runtime.h>
#include <cuda_bf16.h>
#include <cstdint>
#include <math.h>

// ---------------------------------------------------------------------------
// SimpleTransformerBlock via warp-level bf16 mma.sync (sm_103 non-'a' PTX
// target: no tcgen05). fp32 accuracy via bf16 hi/lo split:
// A = [hi|hi|lo], B = [hi|lo|hi], K' = 3K.
// R4: fused splits (attn epilogue, MLP1 epilogue), float4 attn, launch reorder.
// ---------------------------------------------------------------------------

#define M_ROWS 16384

// fp32 scratch
__device__ float g_qkv [(size_t)M_ROWS * 3072];
__device__ float g_x1  [(size_t)M_ROWS * 1024];
// bf16 split scratch
__device__ __nv_bfloat16 g_act  [(size_t)M_ROWS * 3072];     // A split, K=1024
__device__ __nv_bfloat16 g_amlp [(size_t)M_ROWS * 12288];    // A split, K=4096
__device__ __nv_bfloat16 g_ws_qkv [(size_t)3072 * 3072];
__device__ __nv_bfloat16 g_ws_proj[(size_t)1024 * 3072];
__device__ __nv_bfloat16 g_ws_w1  [(size_t)4096 * 3072];
__device__ __nv_bfloat16 g_ws_w2  [(size_t)1024 * 12288];

// ---------------------------------------------------------------------------
// PTX wrappers
// ---------------------------------------------------------------------------
__device__ __forceinline__ uint32_t smem_u32(const void* p) {
    uint32_t a;
    asm("{ .reg .u64 t; cvta.to.shared.u64 t, %1; cvt.u32.u64 %0, t; }" : "=r"(a) : "l"(p));
    return a;
}
__device__ __forceinline__ void cp_async16(uint32_t dst, const void* src) {
    asm volatile("cp.async.cg.shared.global [%0], [%1], 16;" :: "r"(dst), "l"(src));
}
__device__ __forceinline__ void cp_commit() {
    asm volatile("cp.async.commit_group;" ::: "memory");
}
__device__ __forceinline__ void cp_wait1() {
    asm volatile("cp.async.wait_group 1;" ::: "memory");
}
__device__ __forceinline__ void ldsm_x4(uint32_t* r, uint32_t addr) {
    asm volatile("ldmatrix.sync.aligned.m8n8.x4.shared.b16 {%0,%1,%2,%3}, [%4];"
                 : "=r"(r[0]), "=r"(r[1]), "=r"(r[2]), "=r"(r[3]) : "r"(addr));
}
__device__ __forceinline__ void mma16816(float* c, const uint32_t* a, uint32_t b0, uint32_t b1) {
    asm volatile(
        "mma.sync.aligned.m16n8k16.row.col.f32.bf16.bf16.f32 "
        "{%0,%1,%2,%3}, {%4,%5,%6,%7}, {%8,%9}, {%0,%1,%2,%3};"
        : "+f"(c[0]), "+f"(c[1]), "+f"(c[2]), "+f"(c[3])
        : "r"(a[0]), "r"(a[1]), "r"(a[2]), "r"(a[3]), "r"(b0), "r"(b1));
}
__device__ __forceinline__ uint32_t swz(uint32_t off) {   // SW128 (128B rows)
    return off ^ ((off >> 3) & 0x70);
}
__device__ __forceinline__ uint32_t pack_bf16x2(float x, float y) {
    __nv_bfloat162 h = __floats2bfloat162_rn(x, y);
    return *(uint32_t*)&h;
}
__device__ __forceinline__ void split_pair(float x, float y, uint32_t& hi, uint32_t& lo) {
    __nv_bfloat16 hx = __float2bfloat16(x), hy = __float2bfloat16(y);
    hi = ((uint32_t)*(uint16_t*)&hy << 16) | *(uint16_t*)&hx;
    lo = pack_bf16x2(x - __bfloat162float(hx), y - __bfloat162float(hy));
}

// ---------------------------------------------------------------------------
// LayerNorm fused with hi/lo split: out row = [hi(1024) | hi(1024) | lo(1024)]
// ---------------------------------------------------------------------------
__global__ __launch_bounds__(256) void ln_split_kernel(
    const float* __restrict__ x, const float* __restrict__ w,
    const float* __restrict__ b, __nv_bfloat16* __restrict__ out)
{
    const int row = blockIdx.x;
    const int t   = threadIdx.x;
    const float4 v = ((const float4*)(x + (size_t)row * 1024))[t];
    float s  = v.x + v.y + v.z + v.w;
    float sq = v.x*v.x + v.y*v.y + v.z*v.z + v.w*v.w;
    #pragma unroll
    for (int o = 16; o > 0; o >>= 1) {
        s  += __shfl_xor_sync(0xffffffffu, s,  o);
        sq += __shfl_xor_sync(0xffffffffu, sq, o);
    }
    __shared__ float sm[8], sm2[8];
    const int warp = t >> 5, lane = t & 31;
    if (lane == 0) { sm[warp] = s; sm2[warp] = sq; }
    __syncthreads();
    if (t == 0) {
        float a = 0.f, c = 0.f;
        #pragma unroll
        for (int i = 0; i < 8; i++) { a += sm[i]; c += sm2[i]; }
        sm[0] = a; sm2[0] = c;
    }
    __syncthreads();
    const float mean = sm[0]  * (1.f / 1024.f);
    const float var  = sm2[0] * (1.f / 1024.f) - mean * mean;
    const float inv  = rsqrtf(var + 1e-5f);
    const float4 wv = ((const float4*)w)[t];
    const float4 bv = ((const float4*)b)[t];
    const float o0 = (v.x - mean) * inv * wv.x + bv.x;
    const float o1 = (v.y - mean) * inv * wv.y + bv.y;
    const float o2 = (v.z - mean) * inv * wv.z + bv.z;
    const float o3 = (v.w - mean) * inv * wv.w + bv.w;

    uint2 H, L;
    split_pair(o0, o1, H.x, L.x);
    split_pair(o2, o3, H.y, L.y);

    __nv_bfloat16* base = out + (size_t)row * 3072 + t * 4;
    *(uint2*)(base)        = H;
    *(uint2*)(base + 1024) = H;
    *(uint2*)(base + 2048) = L;
}

// ---------------------------------------------------------------------------
// fp32 -> bf16 hi/lo split for weights: [hi | lo | hi] (LO in middle block)
// ---------------------------------------------------------------------------
__global__ __launch_bounds__(256) void split_w_kernel(
    const float* __restrict__ in, __nv_bfloat16* __restrict__ out, int K)
{
    const size_t e = ((size_t)blockIdx.x * 256 + threadIdx.x) * 4;
    const size_t r = e / (size_t)K;
    const int    c = (int)(e - r * (size_t)K);
    const float4 v = *(const float4*)(in + e);

    uint2 H, L;
    split_pair(v.x, v.y, H.x, L.x);
    split_pair(v.z, v.w, H.y, L.y);

    __nv_bfloat16* base = out + r * (size_t)(3 * K) + c;
    *(uint2*)(base)         = H;
    *(uint2*)(base + K)     = L;
    *(uint2*)(base + 2 * K) = H;
}

// ---------------------------------------------------------------------------
// Per-position head-mix attention, float4 LDS, fused hi/lo split output.
// Output layout: act row = [hi(1024) | hi(1024) | lo(1024)]
// ---------------------------------------------------------------------------
__global__ __launch_bounds__(128) void attn_split_kernel(
    const float* __restrict__ qkv, __nv_bfloat16* __restrict__ out)
{
    const int pos = blockIdx.x;
    const int t   = threadIdx.x;
    const float4* base = (const float4*)(qkv + (size_t)pos * 3072);

    __shared__ float4 sq[256], sk[256], sv[256];
    __shared__ float S[16][17];

    sq[t]       = base[t];
    sq[t + 128] = base[t + 128];
    sk[t]       = base[256 + t];
    sk[t + 128] = base[256 + t + 128];
    sv[t]       = base[512 + t];
    sv[t + 128] = base[512 + t + 128];
    __syncthreads();

    // scores: 2 per thread, float4 dot over d
    #pragma unroll
    for (int ee = 0; ee < 2; ee++) {
        const int e = t + ee * 128;
        const int h = e >> 4, g = e & 15;
        float4 a = make_float4(0.f, 0.f, 0.f, 0.f);
        #pragma unroll
        for (int d4 = 0; d4 < 16; d4++) {
            const float4 qv = sq[h * 16 + d4];
            const float4 kv = sk[g * 16 + d4];
            a.x = fmaf(qv.x, kv.x, a.x);
            a.y = fmaf(qv.y, kv.y, a.y);
            a.z = fmaf(qv.z, kv.z, a.z);
            a.w = fmaf(qv.w, kv.w, a.w);
        }
        S[h][g] = (a.x + a.y + a.z + a.w) * 0.125f;
    }
    __syncthreads();

    if (t < 16) {
        float m = -1e30f;
        #pragma unroll
        for (int g = 0; g < 16; g++) m = fmaxf(m, S[t][g]);
        float sum = 0.f;
        #pragma unroll
        for (int g = 0; g < 16; g++) { float e = expf(S[t][g] - m); S[t][g] = e; sum += e; }
        const float inv = 1.f / sum;
        #pragma unroll
        for (int g = 0; g < 16; g++) S[t][g] *= inv;
    }
    __syncthreads();

    // out: 2 float4 per thread; fused hi/lo split store
    __nv_bfloat16* orow = out + (size_t)pos * 3072;
    #pragma unroll
    for (int qq = 0; qq < 2; qq++) {
        const int q  = t + qq * 128;        // float4 index 0..255
        const int h  = q >> 4, d4 = q & 15;
        float4 a = make_float4(0.f, 0.f, 0.f, 0.f);
        #pragma unroll
        for (int g = 0; g < 16; g++) {
            const float p = S[h][g];
            const float4 vv = sv[g * 16 + d4];
            a.x = fmaf(p, vv.x, a.x);
            a.y = fmaf(p, vv.y, a.y);
            a.z = fmaf(p, vv.z, a.z);
            a.w = fmaf(p, vv.w, a.w);
        }
        uint2 H, L;
        split_pair(a.x, a.y, H.x, L.x);
        split_pair(a.z, a.w, H.y, L.y);
        __nv_bfloat16* p0 = orow + q * 4;
        *(uint2*)(p0)        = H;
        *(uint2*)(p0 + 1024) = H;
        *(uint2*)(p0 + 2048) = L;
    }
}

// ---------------------------------------------------------------------------
// bf16 mma.sync GEMM: C = A[M,K3] @ B[N,K3]^T + bias (+res | +gelu[+split])
// BM=BN=128, BK=64, 256 thr (8 warps 4x2, warp tile 32x64), 3-stage cp.async.
// ---------------------------------------------------------------------------
#define STAGES 3
#define STAGE_BYTES 32768

#define EPI_BIAS 0
#define EPI_RES  1
#define EPI_GELU 2

__device__ __forceinline__ float gelu_exact(float v) {
    return 0.5f * v * (1.0f + erff(v * 0.70710678118654752f));
}

template<int EPI, bool SPLIT_OUT>
__global__ __launch_bounds__(256, 2) void gemm_mma(
    int M, int N, int K3,
    const __nv_bfloat16* __restrict__ A,   // [M, K3]
    const __nv_bfloat16* __restrict__ B,   // [N, K3]
    const float* __restrict__ bias,
    const float* __restrict__ res,
    float* __restrict__ C,                 // fp32 out (if !SPLIT_OUT)
    __nv_bfloat16* __restrict__ Cs)        // split out [hi|hi|lo], stride 3N
{
    extern __shared__ char smem[];
    const uint32_t sbase = smem_u32(smem);

    const int tid  = threadIdx.x;
    const int wid  = tid >> 5;
    const int lane = tid & 31;
    const int wm   = wid & 3;
    const int wn   = wid >> 2;

    const int bm = blockIdx.y * 128;
    const int bn = blockIdx.x * 128;
    const __nv_bfloat16* Ab = A + (size_t)bm * K3;
    const __nv_bfloat16* Bb = B + (size_t)bn * K3;

    float acc[2][8][4];
    #pragma unroll
    for (int i = 0; i < 2; i++)
        #pragma unroll
        for (int j = 0; j < 8; j++)
            #pragma unroll
            for (int k = 0; k < 4; k++) acc[i][j][k] = 0.f;

    auto load_stage = [&](int k0, int buf) {
        const uint32_t sA = sbase + buf * STAGE_BYTES;
        const uint32_t sB = sA + 16384;
        #pragma unroll
        for (int i = 0; i < 4; i++) {
            const int idx = tid + (i << 8);
            const int row = idx >> 3;
            const int c8  = (idx & 7) << 3;
            const uint32_t so = swz((uint32_t)(row * 128 + c8 * 2));
            cp_async16(sA + so, Ab + (size_t)row * K3 + k0 + c8);
            cp_async16(sB + so, Bb + (size_t)row * K3 + k0 + c8);
        }
    };

    const int S = K3 >> 6;
    load_stage(0, 0); cp_commit();
    load_stage(64, 1); cp_commit();

    for (int s = 0; s < S; s++) {
        cp_wait1();
        __syncthreads();

        if (s + STAGES - 1 < S) load_stage((s + STAGES - 1) << 6, (s + STAGES - 1) % STAGES);
        cp_commit();

        const uint32_t sA = sbase + (s % STAGES) * STAGE_BYTES;
        const uint32_t sB = sA + 16384;

        #pragma unroll
        for (int ks = 0; ks < 4; ks++) {
            const int chunk = ks * 2 + (lane >> 4);
            uint32_t a[2][4];
            #pragma unroll
            for (int mt = 0; mt < 2; mt++) {
                const int row = wm * 32 + mt * 16 + (lane & 15);
                ldsm_x4(a[mt], sA + swz((uint32_t)(row * 128 + chunk * 16)));
            }
            uint32_t bfr[4][4];
            #pragma unroll
            for (int bt = 0; bt < 4; bt++) {
                const int row = wn * 64 + bt * 16 + (lane & 15);
                ldsm_x4(bfr[bt], sB + swz((uint32_t)(row * 128 + chunk * 16)));
            }
            #pragma unroll
            for (int mt = 0; mt < 2; mt++)
                #pragma unroll
                for (int nt = 0; nt < 8; nt++) {
                    const int bt = nt >> 1, wh = nt & 1;
                    mma16816(acc[mt][nt], a[mt], bfr[bt][wh], bfr[bt][wh + 2]);
                }
        }
        __syncthreads();
    }

    // epilogue
    const int colq = (lane & 3) * 2;
    const int rowq = lane >> 2;
    #pragma unroll
    for (int mt = 0; mt < 2; mt++) {
        #pragma unroll
        for (int nt = 0; nt < 8; nt++) {
            const int col = bn + wn * 64 + nt * 8 + colq;
            const float2 bz = *(const float2*)(bias + col);
            #pragma unroll
            for (int hh = 0; hh < 2; hh++) {
                const int grow = bm + wm * 32 + mt * 16 + rowq + hh * 8;
                float2 v;
                v.x = acc[mt][nt][hh * 2 + 0] + bz.x;
                v.y = acc[mt][nt][hh * 2 + 1] + bz.y;
                if (EPI == EPI_RES) {
                    const float2 r = *(const float2*)(res + (size_t)grow * N + col);
                    v.x += r.x; v.y += r.y;
                }
                if (EPI == EPI_GELU) {
                    v.x = gelu_exact(v.x); v.y = gelu_exact(v.y);
                }
                if (SPLIT_OUT) {
                    uint32_t hi, lo;
                    split_pair(v.x, v.y, hi, lo);
                    __nv_bfloat16* p = Cs + (size_t)grow * (3 * N) + col;
                    *(uint32_t*)(p)         = hi;
                    *(uint32_t*)(p + N)     = hi;
                    *(uint32_t*)(p + 2 * N) = lo;
                } else {
                    *(float2*)(C + (size_t)grow * N + col) = v;
                }
            }
        }
    }
}

// ---------------------------------------------------------------------------
// Launch
// ---------------------------------------------------------------------------
extern "C" void kernel_launch(void* const* d_in, const int* in_sizes, int n_in,
                              void* d_out, int out_size)
{
    const float* x      = (const float*)d_in[0];
    const float* qkv_w  = (const float*)d_in[1];
    const float* qkv_b  = (const float*)d_in[2];
    const float* proj_w = (const float*)d_in[3];
    const float* proj_b = (const float*)d_in[4];
    const float* ln1_w  = (const float*)d_in[5];
    const float* ln1_b  = (const float*)d_in[6];
    const float* ln2_w  = (const float*)d_in[7];
    const float* ln2_b  = (const float*)d_in[8];
    const float* mlp_w1 = (const float*)d_in[9];
    const float* mlp_b1 = (const float*)d_in[10];
    const float* mlp_w2 = (const float*)d_in[11];
    const float* mlp_b2 = (const float*)d_in[12];
    float* out = (float*)d_out;

    float *qkv, *x1;
    __nv_bfloat16 *act, *amlp, *wsq, *wsp, *ws1, *ws2;
    cudaGetSymbolAddress((void**)&qkv,  g_qkv);
    cudaGetSymbolAddress((void**)&x1,   g_x1);
    cudaGetSymbolAddress((void**)&act,  g_act);
    cudaGetSymbolAddress((void**)&amlp, g_amlp);
    cudaGetSymbolAddress((void**)&wsq,  g_ws_qkv);
    cudaGetSymbolAddress((void**)&wsp,  g_ws_proj);
    cudaGetSymbolAddress((void**)&ws1,  g_ws_w1);
    cudaGetSymbolAddress((void**)&ws2,  g_ws_w2);

    const int SMEM = STAGES * STAGE_BYTES;   // 96KB
    cudaFuncSetAttribute(gemm_mma<EPI_BIAS, false>, cudaFuncAttributeMaxDynamicSharedMemorySize, SMEM);
    cudaFuncSetAttribute(gemm_mma<EPI_RES,  false>, cudaFuncAttributeMaxDynamicSharedMemorySize, SMEM);
    cudaFuncSetAttribute(gemm_mma<EPI_GELU, true >, cudaFuncAttributeMaxDynamicSharedMemorySize, SMEM);

    const int M = M_ROWS;

    // 0) weight split (qkv), 1) LN1-split, 2) weight split (proj)
    split_w_kernel<<<3072 * 1024 / 1024, 256>>>(qkv_w, wsq, 1024);
    ln_split_kernel<<<M, 256>>>(x, ln1_w, ln1_b, act);
    split_w_kernel<<<1024 * 1024 / 1024, 256>>>(proj_w, wsp, 1024);

    // 3) qkv GEMM  (profiled launch slot)
    gemm_mma<EPI_BIAS, false><<<dim3(3072 / 128, M / 128), 256, SMEM>>>(
        M, 3072, 3072, act, wsq, qkv_b, nullptr, qkv, nullptr);

    // 4) attention -> act (split, fused)
    attn_split_kernel<<<M, 128>>>(qkv, act);

    // 5) x1 = x + act @ proj^T + proj_b
    gemm_mma<EPI_RES, false><<<dim3(1024 / 128, M / 128), 256, SMEM>>>(
        M, 1024, 3072, act, wsp, proj_b, x, x1, nullptr);

    // 6) act = split(LN2(x1)); 7) weight split w1
    ln_split_kernel<<<M, 256>>>(x1, ln2_w, ln2_b, act);
    split_w_kernel<<<4096 * 1024 / 1024, 256>>>(mlp_w1, ws1, 1024);

    // 8) amlp = split(gelu(act @ w1^T + b1))  (fused split epilogue)
    gemm_mma<EPI_GELU, true><<<dim3(4096 / 128, M / 128), 256, SMEM>>>(
        M, 4096, 3072, act, ws1, mlp_b1, nullptr, nullptr, amlp);

    // 9) weight split w2 (K=4096)
    split_w_kernel<<<1024 * 4096 / 1024, 256>>>(mlp_w2, ws2, 4096);

    // 10) out = x1 + amlp @ w2^T + b2
    gemm_mma<EPI_RES, false><<<dim3(1024 / 128, M / 128), 256, SMEM>>>(
        M, 1024, 12288, amlp, ws2, mlp_b2, x1, out, nullptr);
}

// round 5
// speedup vs baseline: 3.0109x; 1.0822x over previous
#include <cuda_runtime.h>
#include <cuda_bf16.h>
#include <cstdint>
#include <math.h>

// ---------------------------------------------------------------------------
// SimpleTransformerBlock via warp-level bf16 mma.sync (sm_103 non-'a' PTX
// target: no tcgen05). fp32 accuracy via bf16 hi/lo split:
// A = [hi|hi|lo], B = [hi|lo|hi], K' = 3K.
// R5: hoisted swizzle address math (1 LOP per ldsm), 1 barrier per stage.
// ---------------------------------------------------------------------------

#define M_ROWS 16384

// fp32 scratch
__device__ float g_qkv [(size_t)M_ROWS * 3072];
__device__ float g_x1  [(size_t)M_ROWS * 1024];
// bf16 split scratch
__device__ __nv_bfloat16 g_act  [(size_t)M_ROWS * 3072];     // A split, K=1024
__device__ __nv_bfloat16 g_amlp [(size_t)M_ROWS * 12288];    // A split, K=4096
__device__ __nv_bfloat16 g_ws_qkv [(size_t)3072 * 3072];
__device__ __nv_bfloat16 g_ws_proj[(size_t)1024 * 3072];
__device__ __nv_bfloat16 g_ws_w1  [(size_t)4096 * 3072];
__device__ __nv_bfloat16 g_ws_w2  [(size_t)1024 * 12288];

// ---------------------------------------------------------------------------
// PTX wrappers
// ---------------------------------------------------------------------------
__device__ __forceinline__ uint32_t smem_u32(const void* p) {
    uint32_t a;
    asm("{ .reg .u64 t; cvta.to.shared.u64 t, %1; cvt.u32.u64 %0, t; }" : "=r"(a) : "l"(p));
    return a;
}
__device__ __forceinline__ void cp_async16(uint32_t dst, const void* src) {
    asm volatile("cp.async.cg.shared.global [%0], [%1], 16;" :: "r"(dst), "l"(src));
}
__device__ __forceinline__ void cp_commit() {
    asm volatile("cp.async.commit_group;" ::: "memory");
}
__device__ __forceinline__ void cp_wait1() {
    asm volatile("cp.async.wait_group 1;" ::: "memory");
}
__device__ __forceinline__ void ldsm_x4(uint32_t* r, uint32_t addr) {
    asm volatile("ldmatrix.sync.aligned.m8n8.x4.shared.b16 {%0,%1,%2,%3}, [%4];"
                 : "=r"(r[0]), "=r"(r[1]), "=r"(r[2]), "=r"(r[3]) : "r"(addr));
}
__device__ __forceinline__ void mma16816(float* c, const uint32_t* a, uint32_t b0, uint32_t b1) {
    asm volatile(
        "mma.sync.aligned.m16n8k16.row.col.f32.bf16.bf16.f32 "
        "{%0,%1,%2,%3}, {%4,%5,%6,%7}, {%8,%9}, {%0,%1,%2,%3};"
        : "+f"(c[0]), "+f"(c[1]), "+f"(c[2]), "+f"(c[3])
        : "r"(a[0]), "r"(a[1]), "r"(a[2]), "r"(a[3]), "r"(b0), "r"(b1));
}
__device__ __forceinline__ uint32_t pack_bf16x2(float x, float y) {
    __nv_bfloat162 h = __floats2bfloat162_rn(x, y);
    return *(uint32_t*)&h;
}
__device__ __forceinline__ void split_pair(float x, float y, uint32_t& hi, uint32_t& lo) {
    __nv_bfloat16 hx = __float2bfloat16(x), hy = __float2bfloat16(y);
    hi = ((uint32_t)*(uint16_t*)&hy << 16) | *(uint16_t*)&hx;
    lo = pack_bf16x2(x - __bfloat162float(hx), y - __bfloat162float(hy));
}

// ---------------------------------------------------------------------------
// LayerNorm fused with hi/lo split: out row = [hi(1024) | hi(1024) | lo(1024)]
// ---------------------------------------------------------------------------
__global__ __launch_bounds__(256) void ln_split_kernel(
    const float* __restrict__ x, const float* __restrict__ w,
    const float* __restrict__ b, __nv_bfloat16* __restrict__ out)
{
    const int row = blockIdx.x;
    const int t   = threadIdx.x;
    const float4 v = ((const float4*)(x + (size_t)row * 1024))[t];
    float s  = v.x + v.y + v.z + v.w;
    float sq = v.x*v.x + v.y*v.y + v.z*v.z + v.w*v.w;
    #pragma unroll
    for (int o = 16; o > 0; o >>= 1) {
        s  += __shfl_xor_sync(0xffffffffu, s,  o);
        sq += __shfl_xor_sync(0xffffffffu, sq, o);
    }
    __shared__ float sm[8], sm2[8];
    const int warp = t >> 5, lane = t & 31;
    if (lane == 0) { sm[warp] = s; sm2[warp] = sq; }
    __syncthreads();
    if (t == 0) {
        float a = 0.f, c = 0.f;
        #pragma unroll
        for (int i = 0; i < 8; i++) { a += sm[i]; c += sm2[i]; }
        sm[0] = a; sm2[0] = c;
    }
    __syncthreads();
    const float mean = sm[0]  * (1.f / 1024.f);
    const float var  = sm2[0] * (1.f / 1024.f) - mean * mean;
    const float inv  = rsqrtf(var + 1e-5f);
    const float4 wv = ((const float4*)w)[t];
    const float4 bv = ((const float4*)b)[t];
    const float o0 = (v.x - mean) * inv * wv.x + bv.x;
    const float o1 = (v.y - mean) * inv * wv.y + bv.y;
    const float o2 = (v.z - mean) * inv * wv.z + bv.z;
    const float o3 = (v.w - mean) * inv * wv.w + bv.w;

    uint2 H, L;
    split_pair(o0, o1, H.x, L.x);
    split_pair(o2, o3, H.y, L.y);

    __nv_bfloat16* base = out + (size_t)row * 3072 + t * 4;
    *(uint2*)(base)        = H;
    *(uint2*)(base + 1024) = H;
    *(uint2*)(base + 2048) = L;
}

// ---------------------------------------------------------------------------
// fp32 -> bf16 hi/lo split for weights: [hi | lo | hi]
// ---------------------------------------------------------------------------
__global__ __launch_bounds__(256) void split_w_kernel(
    const float* __restrict__ in, __nv_bfloat16* __restrict__ out, int K)
{
    const size_t e = ((size_t)blockIdx.x * 256 + threadIdx.x) * 4;
    const size_t r = e / (size_t)K;
    const int    c = (int)(e - r * (size_t)K);
    const float4 v = *(const float4*)(in + e);

    uint2 H, L;
    split_pair(v.x, v.y, H.x, L.x);
    split_pair(v.z, v.w, H.y, L.y);

    __nv_bfloat16* base = out + r * (size_t)(3 * K) + c;
    *(uint2*)(base)         = H;
    *(uint2*)(base + K)     = L;
    *(uint2*)(base + 2 * K) = H;
}

// ---------------------------------------------------------------------------
// Per-position head-mix attention, float4 LDS, fused hi/lo split output.
// ---------------------------------------------------------------------------
__global__ __launch_bounds__(128) void attn_split_kernel(
    const float* __restrict__ qkv, __nv_bfloat16* __restrict__ out)
{
    const int pos = blockIdx.x;
    const int t   = threadIdx.x;
    const float4* base = (const float4*)(qkv + (size_t)pos * 3072);

    __shared__ float4 sq[256], sk[256], sv[256];
    __shared__ float S[16][17];

    sq[t]       = base[t];
    sq[t + 128] = base[t + 128];
    sk[t]       = base[256 + t];
    sk[t + 128] = base[256 + t + 128];
    sv[t]       = base[512 + t];
    sv[t + 128] = base[512 + t + 128];
    __syncthreads();

    #pragma unroll
    for (int ee = 0; ee < 2; ee++) {
        const int e = t + ee * 128;
        const int h = e >> 4, g = e & 15;
        float4 a = make_float4(0.f, 0.f, 0.f, 0.f);
        #pragma unroll
        for (int d4 = 0; d4 < 16; d4++) {
            const float4 qv = sq[h * 16 + d4];
            const float4 kv = sk[g * 16 + d4];
            a.x = fmaf(qv.x, kv.x, a.x);
            a.y = fmaf(qv.y, kv.y, a.y);
            a.z = fmaf(qv.z, kv.z, a.z);
            a.w = fmaf(qv.w, kv.w, a.w);
        }
        S[h][g] = (a.x + a.y + a.z + a.w) * 0.125f;
    }
    __syncthreads();

    if (t < 16) {
        float m = -1e30f;
        #pragma unroll
        for (int g = 0; g < 16; g++) m = fmaxf(m, S[t][g]);
        float sum = 0.f;
        #pragma unroll
        for (int g = 0; g < 16; g++) { float e = expf(S[t][g] - m); S[t][g] = e; sum += e; }
        const float inv = 1.f / sum;
        #pragma unroll
        for (int g = 0; g < 16; g++) S[t][g] *= inv;
    }
    __syncthreads();

    __nv_bfloat16* orow = out + (size_t)pos * 3072;
    #pragma unroll
    for (int qq = 0; qq < 2; qq++) {
        const int q  = t + qq * 128;
        const int h  = q >> 4, d4 = q & 15;
        float4 a = make_float4(0.f, 0.f, 0.f, 0.f);
        #pragma unroll
        for (int g = 0; g < 16; g++) {
            const float p = S[h][g];
            const float4 vv = sv[g * 16 + d4];
            a.x = fmaf(p, vv.x, a.x);
            a.y = fmaf(p, vv.y, a.y);
            a.z = fmaf(p, vv.z, a.z);
            a.w = fmaf(p, vv.w, a.w);
        }
        uint2 H, L;
        split_pair(a.x, a.y, H.x, L.x);
        split_pair(a.z, a.w, H.y, L.y);
        __nv_bfloat16* p0 = orow + q * 4;
        *(uint2*)(p0)        = H;
        *(uint2*)(p0 + 1024) = H;
        *(uint2*)(p0 + 2048) = L;
    }
}

// ---------------------------------------------------------------------------
// bf16 mma.sync GEMM: C = A[M,K3] @ B[N,K3]^T + bias (+res | +gelu[+split])
// BM=BN=128, BK=64, 256 thr (8 warps 4x2, warp tile 32x64), 3-stage cp.async.
// Swizzle identity: swz(r*128 + c*16) = r*128 + (c*16 ^ ((r&7)<<4)), so every
// ldsm address is (stage_base + R_invariant) ^ (ks*32) — one LOP per ldsm.
// ---------------------------------------------------------------------------
#define STAGES 3
#define STAGE_BYTES 32768

#define EPI_BIAS 0
#define EPI_RES  1
#define EPI_GELU 2

__device__ __forceinline__ float gelu_exact(float v) {
    return 0.5f * v * (1.0f + erff(v * 0.70710678118654752f));
}

template<int EPI, bool SPLIT_OUT>
__global__ __launch_bounds__(256, 2) void gemm_mma(
    int M, int N, int K3,
    const __nv_bfloat16* __restrict__ A,   // [M, K3]
    const __nv_bfloat16* __restrict__ B,   // [N, K3]
    const float* __restrict__ bias,
    const float* __restrict__ res,
    float* __restrict__ C,
    __nv_bfloat16* __restrict__ Cs)        // split out [hi|hi|lo], stride 3N
{
    extern __shared__ char smem[];
    const uint32_t sbase = smem_u32(smem);

    const int tid  = threadIdx.x;
    const int wid  = tid >> 5;
    const int lane = tid & 31;
    const int wm   = wid & 3;
    const int wn   = wid >> 2;

    const int bm = blockIdx.y * 128;
    const int bn = blockIdx.x * 128;

    // ---- loader invariants: 4 chunks/operand/stage, 16B each -------------
    const int l_c8   = (tid & 7) << 3;           // bf16 col within 64
    const int l_row0 = tid >> 3;                 // rows row0 + 32*i
    const __nv_bfloat16* Ag = A + (size_t)(bm + l_row0) * K3 + l_c8;
    const __nv_bfloat16* Bg = B + (size_t)(bn + l_row0) * K3 + l_c8;
    uint32_t sto[4];                             // swizzled store offsets
    #pragma unroll
    for (int i = 0; i < 4; i++) {
        const int r = l_row0 + 32 * i;
        sto[i] = (uint32_t)(r * 128 + ((l_c8 * 2) ^ ((r & 7) << 4)));
    }

    // ---- ldsm invariants --------------------------------------------------
    const uint32_t lh16 = (uint32_t)(lane >> 4) << 4;   // 16B col select
    uint32_t Ra[2], Rb[4];
    #pragma unroll
    for (int mt = 0; mt < 2; mt++) {
        const int r = wm * 32 + mt * 16 + (lane & 15);
        Ra[mt] = (uint32_t)(r * 128) + ((((uint32_t)r & 7) << 4) ^ lh16);
    }
    #pragma unroll
    for (int bt = 0; bt < 4; bt++) {
        const int r = wn * 64 + bt * 16 + (lane & 15);
        Rb[bt] = 16384u + (uint32_t)(r * 128) + ((((uint32_t)r & 7) << 4) ^ lh16);
    }

    float acc[2][8][4];
    #pragma unroll
    for (int i = 0; i < 2; i++)
        #pragma unroll
        for (int j = 0; j < 8; j++)
            #pragma unroll
            for (int k = 0; k < 4; k++) acc[i][j][k] = 0.f;

    auto load_stage = [&](int k0, uint32_t sstage) {
        #pragma unroll
        for (int i = 0; i < 4; i++) {
            const size_t go = (size_t)(32 * i) * K3 + k0;
            cp_async16(sstage + sto[i],          Ag + go);
            cp_async16(sstage + 16384u + sto[i], Bg + go);
        }
    };

    const int S = K3 >> 6;
    load_stage(0,  sbase);               cp_commit();
    load_stage(64, sbase + STAGE_BYTES); cp_commit();

    uint32_t s_cur  = sbase;                       // compute stage base
    uint32_t s_next = sbase + 2 * STAGE_BYTES;     // next load target
    for (int s = 0; s < S; s++) {
        cp_wait1();
        __syncthreads();

        if (s + 2 < S) load_stage((s + 2) << 6, s_next);
        cp_commit();
        s_next += STAGE_BYTES;
        if (s_next == sbase + 3 * STAGE_BYTES) s_next = sbase;

        #pragma unroll
        for (int ks = 0; ks < 4; ks++) {
            const uint32_t kx = (uint32_t)(ks * 32);
            uint32_t a[2][4];
            #pragma unroll
            for (int mt = 0; mt < 2; mt++)
                ldsm_x4(a[mt], (s_cur + Ra[mt]) ^ kx);
            uint32_t bfr[4][4];
            #pragma unroll
            for (int bt = 0; bt < 4; bt++)
                ldsm_x4(bfr[bt], (s_cur + Rb[bt]) ^ kx);
            #pragma unroll
            for (int mt = 0; mt < 2; mt++)
                #pragma unroll
                for (int nt = 0; nt < 8; nt++) {
                    const int bt = nt >> 1, wh = nt & 1;
                    mma16816(acc[mt][nt], a[mt], bfr[bt][wh], bfr[bt][wh + 2]);
                }
        }
        s_cur += STAGE_BYTES;
        if (s_cur == sbase + 3 * STAGE_BYTES) s_cur = sbase;
    }

    // epilogue
    const int colq = (lane & 3) * 2;
    const int rowq = lane >> 2;
    #pragma unroll
    for (int mt = 0; mt < 2; mt++) {
        #pragma unroll
        for (int nt = 0; nt < 8; nt++) {
            const int col = bn + wn * 64 + nt * 8 + colq;
            const float2 bz = *(const float2*)(bias + col);
            #pragma unroll
            for (int hh = 0; hh < 2; hh++) {
                const int grow = bm + wm * 32 + mt * 16 + rowq + hh * 8;
                float2 v;
                v.x = acc[mt][nt][hh * 2 + 0] + bz.x;
                v.y = acc[mt][nt][hh * 2 + 1] + bz.y;
                if (EPI == EPI_RES) {
                    const float2 r = *(const float2*)(res + (size_t)grow * N + col);
                    v.x += r.x; v.y += r.y;
                }
                if (EPI == EPI_GELU) {
                    v.x = gelu_exact(v.x); v.y = gelu_exact(v.y);
                }
                if (SPLIT_OUT) {
                    uint32_t hi, lo;
                    split_pair(v.x, v.y, hi, lo);
                    __nv_bfloat16* p = Cs + (size_t)grow * (3 * N) + col;
                    *(uint32_t*)(p)         = hi;
                    *(uint32_t*)(p + N)     = hi;
                    *(uint32_t*)(p + 2 * N) = lo;
                } else {
                    *(float2*)(C + (size_t)grow * N + col) = v;
                }
            }
        }
    }
}

// ---------------------------------------------------------------------------
// Launch
// ---------------------------------------------------------------------------
extern "C" void kernel_launch(void* const* d_in, const int* in_sizes, int n_in,
                              void* d_out, int out_size)
{
    const float* x      = (const float*)d_in[0];
    const float* qkv_w  = (const float*)d_in[1];
    const float* qkv_b  = (const float*)d_in[2];
    const float* proj_w = (const float*)d_in[3];
    const float* proj_b = (const float*)d_in[4];
    const float* ln1_w  = (const float*)d_in[5];
    const float* ln1_b  = (const float*)d_in[6];
    const float* ln2_w  = (const float*)d_in[7];
    const float* ln2_b  = (const float*)d_in[8];
    const float* mlp_w1 = (const float*)d_in[9];
    const float* mlp_b1 = (const float*)d_in[10];
    const float* mlp_w2 = (const float*)d_in[11];
    const float* mlp_b2 = (const float*)d_in[12];
    float* out = (float*)d_out;

    float *qkv, *x1;
    __nv_bfloat16 *act, *amlp, *wsq, *wsp, *ws1, *ws2;
    cudaGetSymbolAddress((void**)&qkv,  g_qkv);
    cudaGetSymbolAddress((void**)&x1,   g_x1);
    cudaGetSymbolAddress((void**)&act,  g_act);
    cudaGetSymbolAddress((void**)&amlp, g_amlp);
    cudaGetSymbolAddress((void**)&wsq,  g_ws_qkv);
    cudaGetSymbolAddress((void**)&wsp,  g_ws_proj);
    cudaGetSymbolAddress((void**)&ws1,  g_ws_w1);
    cudaGetSymbolAddress((void**)&ws2,  g_ws_w2);

    const int SMEM = STAGES * STAGE_BYTES;   // 96KB
    cudaFuncSetAttribute(gemm_mma<EPI_BIAS, false>, cudaFuncAttributeMaxDynamicSharedMemorySize, SMEM);
    cudaFuncSetAttribute(gemm_mma<EPI_RES,  false>, cudaFuncAttributeMaxDynamicSharedMemorySize, SMEM);
    cudaFuncSetAttribute(gemm_mma<EPI_GELU, true >, cudaFuncAttributeMaxDynamicSharedMemorySize, SMEM);

    const int M = M_ROWS;

    split_w_kernel<<<3072 * 1024 / 1024, 256>>>(qkv_w, wsq, 1024);
    ln_split_kernel<<<M, 256>>>(x, ln1_w, ln1_b, act);
    split_w_kernel<<<1024 * 1024 / 1024, 256>>>(proj_w, wsp, 1024);

    // launch slot 3: profiled
    gemm_mma<EPI_BIAS, false><<<dim3(3072 / 128, M / 128), 256, SMEM>>>(
        M, 3072, 3072, act, wsq, qkv_b, nullptr, qkv, nullptr);

    attn_split_kernel<<<M, 128>>>(qkv, act);

    gemm_mma<EPI_RES, false><<<dim3(1024 / 128, M / 128), 256, SMEM>>>(
        M, 1024, 3072, act, wsp, proj_b, x, x1, nullptr);

    ln_split_kernel<<<M, 256>>>(x1, ln2_w, ln2_b, act);
    split_w_kernel<<<4096 * 1024 / 1024, 256>>>(mlp_w1, ws1, 1024);

    gemm_mma<EPI_GELU, true><<<dim3(4096 / 128, M / 128), 256, SMEM>>>(
        M, 4096, 3072, act, ws1, mlp_b1, nullptr, nullptr, amlp);

    split_w_kernel<<<1024 * 4096 / 1024, 256>>>(mlp_w2, ws2, 4096);

    gemm_mma<EPI_RES, false><<<dim3(1024 / 128, M / 128), 256, SMEM>>>(
        M, 1024, 12288, amlp, ws2, mlp_b2, x1, out, nullptr);
}